// round 3
// baseline (speedup 1.0000x reference)
#include <cuda_runtime.h>
#include <cstdint>

// ---------------------------------------------------------------------------
// Problem constants
// ---------------------------------------------------------------------------
namespace {
constexpr int B_  = 4;
constexpr int N_  = 1024;
constexpr int T_  = 12;
constexpr int C_  = 256;
constexpr int H_  = 8;
constexpr int DK_ = 32;
constexpr int M_  = B_ * N_ * T_;              // 49152 rows
constexpr size_t MC_ = (size_t)M_ * C_;        // 12,582,912 elems per tensor
constexpr float SCALE_ = 0.17677669529663687f; // 1/sqrt(DK)

// GEMM tiling
constexpr int BM = 128, BN = 128, BK = 16, PAD = 4;
}

// Scratch: projected Qf,Kf,Vf,Qs,Ks,Vs  and  4 attention contexts
__device__ float g_proj[6 * MC_];   // ~302 MB
__device__ float g_ctx [4 * MC_];   // ~201 MB

// ---------------------------------------------------------------------------
// f32x2 packed-FMA helpers (FFMA2 — only reachable via PTX)
// ---------------------------------------------------------------------------
__device__ __forceinline__ unsigned long long pack2(float x) {
    unsigned long long r;
    asm("mov.b64 %0, {%1, %1};" : "=l"(r) : "f"(x));
    return r;
}
__device__ __forceinline__ void ffma2(unsigned long long& c,
                                      unsigned long long a,
                                      unsigned long long b) {
    asm("fma.rn.f32x2 %0, %1, %2, %0;" : "+l"(c) : "l"(a), "l"(b));
}
__device__ __forceinline__ float2 unpack2(unsigned long long v) {
    float2 f;
    asm("mov.b64 {%0, %1}, %2;" : "=f"(f.x), "=f"(f.y) : "l"(v));
    return f;
}

// ---------------------------------------------------------------------------
// 128x128x16 fp32 SGEMM tile body:  Y[m,n] = sum_c X[m,c] * W[n,c]  (+ bias)
// Both X and W are row-major over c (torch Linear y = x @ w.T).
// blockIdx.x -> n tile (fastest: both n-tiles of an m-tile hit L2 for X),
// blockIdx.y -> m tile.  256 threads, 8x8 microtile per thread (as 8x4 f32x2).
// ---------------------------------------------------------------------------
__device__ __forceinline__ void compute_block(
    unsigned long long acc[8][4],
    const float (*As)[BM + PAD], const float (*Bs)[BN + PAD],
    int ty, int tx)
{
#pragma unroll
    for (int k = 0; k < BK; ++k) {
        float4 a0 = *(const float4*)&As[k][ty * 8];
        float4 a1 = *(const float4*)&As[k][ty * 8 + 4];
        ulonglong2 b0 = *(const ulonglong2*)&Bs[k][tx * 8];
        ulonglong2 b1 = *(const ulonglong2*)&Bs[k][tx * 8 + 4];
        float av[8] = {a0.x, a0.y, a0.z, a0.w, a1.x, a1.y, a1.z, a1.w};
        unsigned long long bb[4] = {b0.x, b0.y, b1.x, b1.y};
#pragma unroll
        for (int i = 0; i < 8; ++i) {
            unsigned long long ap = pack2(av[i]);
#pragma unroll
            for (int j = 0; j < 4; ++j) ffma2(acc[i][j], ap, bb[j]);
        }
    }
}

template <bool HAS_BIAS>
__device__ __forceinline__ void gemm_body(
    const float* __restrict__ X, const float* __restrict__ W,
    const float* __restrict__ bias, float* __restrict__ Y)
{
    __shared__ __align__(16) float As[BK][BM + PAD];
    __shared__ __align__(16) float Bs[BK][BN + PAD];

    const int tid = threadIdx.x;
    const int tx = tid & 15;   // n direction (0..15)
    const int ty = tid >> 4;   // m direction (0..15)
    const int n0 = blockIdx.x * BN;
    const int m0 = blockIdx.y * BM;

    // loader mapping: 512 float4 per operand tile, 2 per thread
    const int lr = tid >> 2;          // row 0..63 (+64 for second)
    const int lk = (tid & 3) * 4;     // k offset in {0,4,8,12}

    unsigned long long acc[8][4];
#pragma unroll
    for (int i = 0; i < 8; ++i)
#pragma unroll
        for (int j = 0; j < 4; ++j) acc[i][j] = 0ull;

    float4 ra0, ra1, rb0, rb1;

    // prologue: tile 0
    {
        const float* xp = X + (size_t)(m0 + lr) * C_ + lk;
        ra0 = *(const float4*)xp;
        ra1 = *(const float4*)(xp + (size_t)64 * C_);
        const float* wp = W + (size_t)(n0 + lr) * C_ + lk;
        rb0 = *(const float4*)wp;
        rb1 = *(const float4*)(wp + (size_t)64 * C_);
    }
    {
        As[lk + 0][lr] = ra0.x; As[lk + 1][lr] = ra0.y; As[lk + 2][lr] = ra0.z; As[lk + 3][lr] = ra0.w;
        As[lk + 0][lr + 64] = ra1.x; As[lk + 1][lr + 64] = ra1.y; As[lk + 2][lr + 64] = ra1.z; As[lk + 3][lr + 64] = ra1.w;
        Bs[lk + 0][lr] = rb0.x; Bs[lk + 1][lr] = rb0.y; Bs[lk + 2][lr] = rb0.z; Bs[lk + 3][lr] = rb0.w;
        Bs[lk + 0][lr + 64] = rb1.x; Bs[lk + 1][lr + 64] = rb1.y; Bs[lk + 2][lr + 64] = rb1.z; Bs[lk + 3][lr + 64] = rb1.w;
    }
    __syncthreads();

#pragma unroll 1
    for (int kt = 1; kt < C_ / BK; ++kt) {
        // prefetch next tile to registers
        {
            const float* xp = X + (size_t)(m0 + lr) * C_ + kt * BK + lk;
            ra0 = *(const float4*)xp;
            ra1 = *(const float4*)(xp + (size_t)64 * C_);
            const float* wp = W + (size_t)(n0 + lr) * C_ + kt * BK + lk;
            rb0 = *(const float4*)wp;
            rb1 = *(const float4*)(wp + (size_t)64 * C_);
        }
        compute_block(acc, As, Bs, ty, tx);
        __syncthreads();
        {
            As[lk + 0][lr] = ra0.x; As[lk + 1][lr] = ra0.y; As[lk + 2][lr] = ra0.z; As[lk + 3][lr] = ra0.w;
            As[lk + 0][lr + 64] = ra1.x; As[lk + 1][lr + 64] = ra1.y; As[lk + 2][lr + 64] = ra1.z; As[lk + 3][lr + 64] = ra1.w;
            Bs[lk + 0][lr] = rb0.x; Bs[lk + 1][lr] = rb0.y; Bs[lk + 2][lr] = rb0.z; Bs[lk + 3][lr] = rb0.w;
            Bs[lk + 0][lr + 64] = rb1.x; Bs[lk + 1][lr + 64] = rb1.y; Bs[lk + 2][lr + 64] = rb1.z; Bs[lk + 3][lr + 64] = rb1.w;
        }
        __syncthreads();
    }
    compute_block(acc, As, Bs, ty, tx);

    // epilogue
    const int n = n0 + tx * 8;
    float bv[8];
    if (HAS_BIAS) {
        float4 bb0 = *(const float4*)&bias[n];
        float4 bb1 = *(const float4*)&bias[n + 4];
        bv[0] = bb0.x; bv[1] = bb0.y; bv[2] = bb0.z; bv[3] = bb0.w;
        bv[4] = bb1.x; bv[5] = bb1.y; bv[6] = bb1.z; bv[7] = bb1.w;
    }
#pragma unroll
    for (int i = 0; i < 8; ++i) {
        const int m = m0 + ty * 8 + i;
        float2 p0 = unpack2(acc[i][0]);
        float2 p1 = unpack2(acc[i][1]);
        float2 p2 = unpack2(acc[i][2]);
        float2 p3 = unpack2(acc[i][3]);
        float4 o0 = make_float4(p0.x, p0.y, p1.x, p1.y);
        float4 o1 = make_float4(p2.x, p2.y, p3.x, p3.y);
        if (HAS_BIAS) {
            o0.x += bv[0]; o0.y += bv[1]; o0.z += bv[2]; o0.w += bv[3];
            o1.x += bv[4]; o1.y += bv[5]; o1.z += bv[6]; o1.w += bv[7];
        }
        *(float4*)&Y[(size_t)m * C_ + n]     = o0;
        *(float4*)&Y[(size_t)m * C_ + n + 4] = o1;
    }
}

// ---------------------------------------------------------------------------
// Kernel 1: 6 input projections (blockIdx.z selects tensor/weight pair)
// ---------------------------------------------------------------------------
__global__ __launch_bounds__(256) void k_proj(
    const float* __restrict__ x0, const float* __restrict__ x1,
    const float* __restrict__ x2, const float* __restrict__ x3,
    const float* __restrict__ x4, const float* __restrict__ x5,
    const float* __restrict__ w0, const float* __restrict__ w1,
    const float* __restrict__ w2, const float* __restrict__ w3,
    const float* __restrict__ w4, const float* __restrict__ w5)
{
    const int z = blockIdx.z;
    const float* X;
    const float* W;
    if      (z == 0) { X = x0; W = w0; }
    else if (z == 1) { X = x1; W = w1; }
    else if (z == 2) { X = x2; W = w2; }
    else if (z == 3) { X = x3; W = w3; }
    else if (z == 4) { X = x4; W = w4; }
    else             { X = x5; W = w5; }
    gemm_body<false>(X, W, nullptr, g_proj + (size_t)z * MC_);
}

// ---------------------------------------------------------------------------
// Kernel 2: fused 4-way temporal attention.
// Grid: B*N CTAs. 8 warps/CTA, warp = head, lane = DK index.
// All tiles (T=12, DK=32) register-resident; scores by shfl_xor butterflies.
// ---------------------------------------------------------------------------
__device__ __forceinline__ void attn_one(
    const float a[T_], const float b[T_], const float v[T_],
    float* __restrict__ out)
{
#pragma unroll
    for (int t = 0; t < T_; ++t) {
        float p[T_];
#pragma unroll
        for (int j = 0; j < T_; ++j) p[j] = a[t] * b[j];
        // full-warp reduce (DK=32 spans all lanes); all lanes end with all scores
#pragma unroll
        for (int j = 0; j < T_; ++j) p[j] += __shfl_xor_sync(0xffffffffu, p[j], 16);
#pragma unroll
        for (int j = 0; j < T_; ++j) p[j] += __shfl_xor_sync(0xffffffffu, p[j], 8);
#pragma unroll
        for (int j = 0; j < T_; ++j) p[j] += __shfl_xor_sync(0xffffffffu, p[j], 4);
#pragma unroll
        for (int j = 0; j < T_; ++j) p[j] += __shfl_xor_sync(0xffffffffu, p[j], 2);
#pragma unroll
        for (int j = 0; j < T_; ++j) p[j] += __shfl_xor_sync(0xffffffffu, p[j], 1);

        float mx = p[0];
#pragma unroll
        for (int j = 1; j < T_; ++j) mx = fmaxf(mx, p[j]);
        float sum = 0.f;
        float e[T_];
#pragma unroll
        for (int j = 0; j < T_; ++j) { e[j] = __expf((p[j] - mx) * SCALE_); sum += e[j]; }
        const float inv = 1.0f / sum;
        float acc = 0.f;
#pragma unroll
        for (int j = 0; j < T_; ++j) acc += e[j] * v[j];
        out[(size_t)t * C_] = acc * inv;
    }
}

__global__ __launch_bounds__(256) void k_attn(
    const float* __restrict__ kj, const float* __restrict__ vfs)
{
    const int bn = blockIdx.x;                 // b*N + n
    const int h  = threadIdx.x >> 5;           // head
    const int d  = threadIdx.x & 31;           // DK lane
    const size_t base = (size_t)bn * T_ * C_ + h * DK_ + d;

    const float* Qf = g_proj + 0 * MC_;
    const float* Kf = g_proj + 1 * MC_;
    const float* Vf = g_proj + 2 * MC_;
    const float* Qs = g_proj + 3 * MC_;
    const float* Ks = g_proj + 4 * MC_;
    const float* Vs = g_proj + 5 * MC_;

    float qf[T_], kf[T_], vf[T_], qs[T_], ks[T_], vs[T_], qfs[T_];
#pragma unroll
    for (int t = 0; t < T_; ++t) {
        const size_t o = base + (size_t)t * C_;
        qf[t] = Qf[o]; kf[t] = Kf[o]; vf[t] = Vf[o];
        qs[t] = Qs[o]; ks[t] = Ks[o]; vs[t] = Vs[o];
    }
    // FlowSpeed physics transform: kj * (Qs - Qs^2 / (vf_fs + 1e-5))
#pragma unroll
    for (int t = 0; t < T_; ++t) {
        const float kjt = kj[t];
        const float den = vfs[t] + 1e-5f;
        qfs[t] = kjt * (qs[t] - qs[t] * qs[t] / den);
    }

    attn_one(qf, kf,  vf, g_ctx + 0 * MC_ + base);   // z_ff @ Vf
    attn_one(kf, qfs, vf, g_ctx + 1 * MC_ + base);   // z_fs @ Vf
    attn_one(ks, qf,  vs, g_ctx + 2 * MC_ + base);   // z_sf @ Vs
    attn_one(qs, ks,  vs, g_ctx + 3 * MC_ + base);   // z_ss @ Vs
}

// ---------------------------------------------------------------------------
// Kernel 3: 4 output projections (shared w_out + b_out), write to d_out blocks
// ---------------------------------------------------------------------------
__global__ __launch_bounds__(256) void k_out(
    const float* __restrict__ w, const float* __restrict__ bias,
    float* __restrict__ out)
{
    const int z = blockIdx.z;
    gemm_body<true>(g_ctx + (size_t)z * MC_, w, bias, out + (size_t)z * MC_);
}

// ---------------------------------------------------------------------------
// Entry point
// ---------------------------------------------------------------------------
extern "C" void kernel_launch(void* const* d_in, const int* /*in_sizes*/,
                              int /*n_in*/, void* d_out, int /*out_size*/)
{
    const float* flow_q  = (const float*)d_in[0];
    const float* flow_k  = (const float*)d_in[1];
    const float* flow_v  = (const float*)d_in[2];
    const float* speed_q = (const float*)d_in[3];
    const float* speed_k = (const float*)d_in[4];
    const float* speed_v = (const float*)d_in[5];
    const float* w_fq  = (const float*)d_in[6];
    const float* w_fk  = (const float*)d_in[7];
    const float* w_fv  = (const float*)d_in[8];
    const float* w_sq  = (const float*)d_in[9];
    const float* w_sk  = (const float*)d_in[10];
    const float* w_sv  = (const float*)d_in[11];
    const float* w_out = (const float*)d_in[12];
    const float* b_out = (const float*)d_in[13];
    const float* kj    = (const float*)d_in[14];
    const float* vf_fs = (const float*)d_in[15];

    dim3 gp(C_ / BN, M_ / BM, 6);   // (2, 384, 6)
    k_proj<<<gp, 256>>>(flow_q, flow_k, flow_v, speed_q, speed_k, speed_v,
                        w_fq, w_fk, w_fv, w_sq, w_sk, w_sv);

    k_attn<<<B_ * N_, 256>>>(kj, vf_fs);

    dim3 go(C_ / BN, M_ / BM, 4);   // (2, 384, 4)
    k_out<<<go, 256>>>(w_out, b_out, (float*)d_out);
}

// round 5
// speedup vs baseline: 1.4309x; 1.4309x over previous
#include <cuda_runtime.h>
#include <cuda_bf16.h>
#include <cstdint>

// ---------------------------------------------------------------------------
// Problem constants
// ---------------------------------------------------------------------------
namespace {
constexpr int B_  = 4;
constexpr int N_  = 1024;
constexpr int T_  = 12;
constexpr int C_  = 256;
constexpr int DK_ = 32;
constexpr int M_  = B_ * N_ * T_;              // 49152 rows
constexpr size_t MC_ = (size_t)M_ * C_;        // 12,582,912 elems per tensor
constexpr float SCALE_ = 0.17677669529663687f; // 1/sqrt(DK)

// GEMM tiling (mma.sync m16n8k16 bf16)
constexpr int BM = 128, BN = 128, BK = 32;
constexpr int NKT = C_ / BK;                   // 8 mainloop iterations
constexpr int LDS = 40;                        // smem row stride in bf16 (80 B)
}

// ---------------------------------------------------------------------------
// Device scratch
// ---------------------------------------------------------------------------
__device__ float          g_proj[6 * MC_];      // fp32 projected Q/K/V
__device__ float          g_ctx [4 * MC_];      // fp32 attention contexts
__device__ __nv_bfloat16  g_w_h[7 * C_ * C_];   // bf16 hi of 7 weights
__device__ __nv_bfloat16  g_w_l[7 * C_ * C_];   // bf16 lo of 7 weights

// ---------------------------------------------------------------------------
// PTX helpers (baseline ISA only — no 'a'-suffix features)
// ---------------------------------------------------------------------------
__device__ __forceinline__ uint32_t cvta_s(const void* p) {
    uint32_t a;
    asm("{ .reg .u64 t; cvta.to.shared.u64 t, %1; cvt.u32.u64 %0, t; }"
        : "=r"(a) : "l"(p));
    return a;
}
__device__ __forceinline__ void ldsm4(uint32_t* r, uint32_t addr) {
    asm volatile("ldmatrix.sync.aligned.m8n8.x4.shared.b16 {%0,%1,%2,%3}, [%4];"
                 : "=r"(r[0]), "=r"(r[1]), "=r"(r[2]), "=r"(r[3]) : "r"(addr));
}
__device__ __forceinline__ void mma_bf16(float* d, const uint32_t* a,
                                         const uint32_t* b) {
    asm volatile(
        "mma.sync.aligned.m16n8k16.row.col.f32.bf16.bf16.f32 "
        "{%0,%1,%2,%3}, {%4,%5,%6,%7}, {%8,%9}, {%0,%1,%2,%3};"
        : "+f"(d[0]), "+f"(d[1]), "+f"(d[2]), "+f"(d[3])
        : "r"(a[0]), "r"(a[1]), "r"(a[2]), "r"(a[3]), "r"(b[0]), "r"(b[1]));
}
__device__ __forceinline__ uint32_t pack_bf2(float a, float b) {
    __nv_bfloat162 t = __floats2bfloat162_rn(a, b);
    return *reinterpret_cast<uint32_t*>(&t);
}

// ---------------------------------------------------------------------------
// Weight fp32 -> bf16 hi/lo split (7 weights, 256x256 each; tiny)
// ---------------------------------------------------------------------------
__global__ __launch_bounds__(256) void k_cvt_w(
    const float* __restrict__ w0, const float* __restrict__ w1,
    const float* __restrict__ w2, const float* __restrict__ w3,
    const float* __restrict__ w4, const float* __restrict__ w5,
    const float* __restrict__ w6)
{
    const int z = blockIdx.y;
    const float* s;
    if      (z == 0) s = w0;
    else if (z == 1) s = w1;
    else if (z == 2) s = w2;
    else if (z == 3) s = w3;
    else if (z == 4) s = w4;
    else if (z == 5) s = w5;
    else             s = w6;
    const size_t i = (size_t)blockIdx.x * blockDim.x + threadIdx.x; // float4 idx
    const size_t n4 = (size_t)C_ * C_ / 4;
    if (i >= n4) return;
    float4 v = ((const float4*)s)[i];
    float h0 = __bfloat162float(__float2bfloat16(v.x));
    float h1 = __bfloat162float(__float2bfloat16(v.y));
    float h2 = __bfloat162float(__float2bfloat16(v.z));
    float h3 = __bfloat162float(__float2bfloat16(v.w));
    uint32_t* hp = (uint32_t*)(g_w_h + (size_t)z * C_ * C_) + 2 * i;
    uint32_t* lp = (uint32_t*)(g_w_l + (size_t)z * C_ * C_) + 2 * i;
    hp[0] = pack_bf2(h0, h1);
    hp[1] = pack_bf2(h2, h3);
    lp[0] = pack_bf2(v.x - h0, v.y - h1);
    lp[1] = pack_bf2(v.z - h2, v.w - h3);
}

// ---------------------------------------------------------------------------
// 3-term bf16 mma.sync GEMM:  Y[m,n] = sum_c X[m,c] * W[n,c]  (+ bias)
// X is fp32 in gmem (split to hi/lo inside the loader); W pre-split bf16.
// 256 threads, 8 warps in 2(m) x 4(n), warp tile 64x32, m16n8k16.
// ---------------------------------------------------------------------------
template <bool HAS_BIAS>
__device__ __forceinline__ void mma_gemm(
    const float* __restrict__ X,
    const __nv_bfloat16* __restrict__ Wh, const __nv_bfloat16* __restrict__ Wl,
    const float* __restrict__ bias, float* __restrict__ Y)
{
    __shared__ __align__(16) __nv_bfloat16 sAh[BM * LDS];
    __shared__ __align__(16) __nv_bfloat16 sAl[BM * LDS];
    __shared__ __align__(16) __nv_bfloat16 sBh[BN * LDS];
    __shared__ __align__(16) __nv_bfloat16 sBl[BN * LDS];

    const int tid  = threadIdx.x;
    const int lane = tid & 31;
    const int wid  = tid >> 5;
    const int wm   = (wid >> 2) * 64;   // warp m offset within CTA tile
    const int wn   = (wid & 3) * 32;    // warp n offset
    const int m0 = blockIdx.y * BM;
    const int n0 = blockIdx.x * BN;

    const uint32_t a_ah = cvta_s(sAh), a_al = cvta_s(sAl);
    const uint32_t a_bh = cvta_s(sBh), a_bl = cvta_s(sBl);

    // ldmatrix per-lane byte offsets
    uint32_t aoff[4][2], boff[2][2];
    {
        const int ra = wm + (lane & 7) + ((lane >> 3) & 1) * 8;
        const int ca = (lane >> 4) * 8;
#pragma unroll
        for (int im = 0; im < 4; ++im)
#pragma unroll
            for (int ks = 0; ks < 2; ++ks)
                aoff[im][ks] = (uint32_t)(((ra + im * 16) * LDS + ca + ks * 16) * 2);
        const int rb = wn + (lane & 7) + (lane >> 4) * 8;
        const int cb = ((lane >> 3) & 1) * 8;
#pragma unroll
        for (int ip = 0; ip < 2; ++ip)
#pragma unroll
            for (int ks = 0; ks < 2; ++ks)
                boff[ip][ks] = (uint32_t)(((rb + ip * 16) * LDS + cb + ks * 16) * 2);
    }

    float acc[4][4][4];
#pragma unroll
    for (int im = 0; im < 4; ++im)
#pragma unroll
        for (int in = 0; in < 4; ++in)
#pragma unroll
            for (int q = 0; q < 4; ++q) acc[im][in][q] = 0.f;

    // loader mapping: 2 threads per row; each covers 16 k-columns
    const int lrow = tid >> 1;
    const int lh   = tid & 1;
    const float* xg = X + (size_t)(m0 + lrow) * C_ + lh * 16;
    const __nv_bfloat16* whg = Wh + (size_t)(n0 + lrow) * C_ + lh * 16;
    const __nv_bfloat16* wlg = Wl + (size_t)(n0 + lrow) * C_ + lh * 16;
    uint4* pAh = (uint4*)(sAh + lrow * LDS + lh * 16);
    uint4* pAl = (uint4*)(sAl + lrow * LDS + lh * 16);
    uint4* pBh = (uint4*)(sBh + lrow * LDS + lh * 16);
    uint4* pBl = (uint4*)(sBl + lrow * LDS + lh * 16);

    float4 xv[4];
    uint4  wh2[2], wl2[2];

    // prefetch tile 0
    {
        const float4* xp = (const float4*)xg;
        xv[0] = xp[0]; xv[1] = xp[1]; xv[2] = xp[2]; xv[3] = xp[3];
        const uint4* whp = (const uint4*)whg;
        const uint4* wlp = (const uint4*)wlg;
        wh2[0] = whp[0]; wh2[1] = whp[1];
        wl2[0] = wlp[0]; wl2[1] = wlp[1];
    }

#pragma unroll 1
    for (int kt = 0; kt < NKT; ++kt) {
        __syncthreads();   // previous iteration's consumers done
        // convert + store X, store W
        {
            uint32_t hh[8], ll[8];
#pragma unroll
            for (int q = 0; q < 4; ++q) {
                const float4 v = xv[q];
                float h0 = __bfloat162float(__float2bfloat16(v.x));
                float h1 = __bfloat162float(__float2bfloat16(v.y));
                float h2 = __bfloat162float(__float2bfloat16(v.z));
                float h3 = __bfloat162float(__float2bfloat16(v.w));
                hh[q * 2 + 0] = pack_bf2(h0, h1);
                hh[q * 2 + 1] = pack_bf2(h2, h3);
                ll[q * 2 + 0] = pack_bf2(v.x - h0, v.y - h1);
                ll[q * 2 + 1] = pack_bf2(v.z - h2, v.w - h3);
            }
            pAh[0] = make_uint4(hh[0], hh[1], hh[2], hh[3]);
            pAh[1] = make_uint4(hh[4], hh[5], hh[6], hh[7]);
            pAl[0] = make_uint4(ll[0], ll[1], ll[2], ll[3]);
            pAl[1] = make_uint4(ll[4], ll[5], ll[6], ll[7]);
            pBh[0] = wh2[0]; pBh[1] = wh2[1];
            pBl[0] = wl2[0]; pBl[1] = wl2[1];
        }
        __syncthreads();   // tile visible

        if (kt < NKT - 1) {
            const float4* xp = (const float4*)(xg + (kt + 1) * BK);
            xv[0] = xp[0]; xv[1] = xp[1]; xv[2] = xp[2]; xv[3] = xp[3];
            const uint4* whp = (const uint4*)(whg + (kt + 1) * BK);
            const uint4* wlp = (const uint4*)(wlg + (kt + 1) * BK);
            wh2[0] = whp[0]; wh2[1] = whp[1];
            wl2[0] = wlp[0]; wl2[1] = wlp[1];
        }

#pragma unroll
        for (int ks = 0; ks < 2; ++ks) {
            uint32_t ah[4][4], al[4][4], bh[2][4], bl[2][4];
#pragma unroll
            for (int im = 0; im < 4; ++im) {
                ldsm4(ah[im], a_ah + aoff[im][ks]);
                ldsm4(al[im], a_al + aoff[im][ks]);
            }
#pragma unroll
            for (int ip = 0; ip < 2; ++ip) {
                ldsm4(bh[ip], a_bh + boff[ip][ks]);
                ldsm4(bl[ip], a_bl + boff[ip][ks]);
            }
#pragma unroll
            for (int im = 0; im < 4; ++im) {
#pragma unroll
                for (int in = 0; in < 4; ++in) {
                    const uint32_t* bph = &bh[in >> 1][(in & 1) * 2];
                    const uint32_t* bpl = &bl[in >> 1][(in & 1) * 2];
                    mma_bf16(acc[im][in], ah[im], bph);  // hi * w_hi
                    mma_bf16(acc[im][in], ah[im], bpl);  // hi * w_lo
                    mma_bf16(acc[im][in], al[im], bph);  // lo * w_hi
                }
            }
        }
    }

    // epilogue: d0,d1 -> (row, col..col+1); d2,d3 -> (row+8, col..col+1)
    const int er = lane >> 2;
    const int ec = (lane & 3) * 2;
#pragma unroll
    for (int im = 0; im < 4; ++im) {
#pragma unroll
        for (int in = 0; in < 4; ++in) {
            const int row = m0 + wm + im * 16 + er;
            const int col = n0 + wn + in * 8 + ec;
            float b0 = 0.f, b1 = 0.f;
            if (HAS_BIAS) { b0 = bias[col]; b1 = bias[col + 1]; }
            float2 v0 = make_float2(acc[im][in][0] + b0, acc[im][in][1] + b1);
            float2 v1 = make_float2(acc[im][in][2] + b0, acc[im][in][3] + b1);
            *(float2*)&Y[(size_t)row * C_ + col]       = v0;
            *(float2*)&Y[(size_t)(row + 8) * C_ + col] = v1;
        }
    }
}

__global__ __launch_bounds__(256) void k_mma_proj(
    const float* __restrict__ x0, const float* __restrict__ x1,
    const float* __restrict__ x2, const float* __restrict__ x3,
    const float* __restrict__ x4, const float* __restrict__ x5)
{
    const int z = blockIdx.z;
    const float* X;
    if      (z == 0) X = x0;
    else if (z == 1) X = x1;
    else if (z == 2) X = x2;
    else if (z == 3) X = x3;
    else if (z == 4) X = x4;
    else             X = x5;
    mma_gemm<false>(X, g_w_h + (size_t)z * C_ * C_, g_w_l + (size_t)z * C_ * C_,
                    nullptr, g_proj + (size_t)z * MC_);
}

__global__ __launch_bounds__(256) void k_mma_out(
    const float* __restrict__ bias, float* __restrict__ out)
{
    const int z = blockIdx.z;
    mma_gemm<true>(g_ctx + (size_t)z * MC_,
                   g_w_h + (size_t)6 * C_ * C_, g_w_l + (size_t)6 * C_ * C_,
                   bias, out + (size_t)z * MC_);
}

// ---------------------------------------------------------------------------
// Fused 4-way temporal attention (proven R3 version, fp32 ctx out).
// Grid: B*N CTAs. 8 warps/CTA, warp = head, lane = DK index.
// ---------------------------------------------------------------------------
__device__ __forceinline__ void attn_one(
    const float a[T_], const float b[T_], const float v[T_],
    float* __restrict__ out)
{
#pragma unroll
    for (int t = 0; t < T_; ++t) {
        float p[T_];
#pragma unroll
        for (int j = 0; j < T_; ++j) p[j] = a[t] * b[j];
#pragma unroll
        for (int j = 0; j < T_; ++j) p[j] += __shfl_xor_sync(0xffffffffu, p[j], 16);
#pragma unroll
        for (int j = 0; j < T_; ++j) p[j] += __shfl_xor_sync(0xffffffffu, p[j], 8);
#pragma unroll
        for (int j = 0; j < T_; ++j) p[j] += __shfl_xor_sync(0xffffffffu, p[j], 4);
#pragma unroll
        for (int j = 0; j < T_; ++j) p[j] += __shfl_xor_sync(0xffffffffu, p[j], 2);
#pragma unroll
        for (int j = 0; j < T_; ++j) p[j] += __shfl_xor_sync(0xffffffffu, p[j], 1);

        float mx = p[0];
#pragma unroll
        for (int j = 1; j < T_; ++j) mx = fmaxf(mx, p[j]);
        float sum = 0.f;
        float e[T_];
#pragma unroll
        for (int j = 0; j < T_; ++j) { e[j] = __expf((p[j] - mx) * SCALE_); sum += e[j]; }
        const float inv = 1.0f / sum;
        float acc = 0.f;
#pragma unroll
        for (int j = 0; j < T_; ++j) acc += e[j] * v[j];
        out[(size_t)t * C_] = acc * inv;
    }
}

__global__ __launch_bounds__(256) void k_attn(
    const float* __restrict__ kj, const float* __restrict__ vfs)
{
    const int bn = blockIdx.x;
    const int h  = threadIdx.x >> 5;
    const int d  = threadIdx.x & 31;
    const size_t base = (size_t)bn * T_ * C_ + h * DK_ + d;

    const float* Qf = g_proj + 0 * MC_;
    const float* Kf = g_proj + 1 * MC_;
    const float* Vf = g_proj + 2 * MC_;
    const float* Qs = g_proj + 3 * MC_;
    const float* Ks = g_proj + 4 * MC_;
    const float* Vs = g_proj + 5 * MC_;

    float qf[T_], kf[T_], vf[T_], qs[T_], ks[T_], vs[T_], qfs[T_];
#pragma unroll
    for (int t = 0; t < T_; ++t) {
        const size_t o = base + (size_t)t * C_;
        qf[t] = Qf[o]; kf[t] = Kf[o]; vf[t] = Vf[o];
        qs[t] = Qs[o]; ks[t] = Ks[o]; vs[t] = Vs[o];
    }
#pragma unroll
    for (int t = 0; t < T_; ++t) {
        const float kjt = kj[t];
        const float den = vfs[t] + 1e-5f;
        qfs[t] = kjt * (qs[t] - qs[t] * qs[t] / den);
    }

    attn_one(qf, kf,  vf, g_ctx + 0 * MC_ + base);   // z_ff @ Vf
    attn_one(kf, qfs, vf, g_ctx + 1 * MC_ + base);   // z_fs @ Vf
    attn_one(ks, qf,  vs, g_ctx + 2 * MC_ + base);   // z_sf @ Vs
    attn_one(qs, ks,  vs, g_ctx + 3 * MC_ + base);   // z_ss @ Vs
}

// ---------------------------------------------------------------------------
// Entry point
// ---------------------------------------------------------------------------
extern "C" void kernel_launch(void* const* d_in, const int* /*in_sizes*/,
                              int /*n_in*/, void* d_out, int /*out_size*/)
{
    const float* flow_q  = (const float*)d_in[0];
    const float* flow_k  = (const float*)d_in[1];
    const float* flow_v  = (const float*)d_in[2];
    const float* speed_q = (const float*)d_in[3];
    const float* speed_k = (const float*)d_in[4];
    const float* speed_v = (const float*)d_in[5];
    const float* w_fq  = (const float*)d_in[6];
    const float* w_fk  = (const float*)d_in[7];
    const float* w_fv  = (const float*)d_in[8];
    const float* w_sq  = (const float*)d_in[9];
    const float* w_sk  = (const float*)d_in[10];
    const float* w_sv  = (const float*)d_in[11];
    const float* w_out = (const float*)d_in[12];
    const float* b_out = (const float*)d_in[13];
    const float* kj    = (const float*)d_in[14];
    const float* vf_fs = (const float*)d_in[15];

    // 1. weight fp32 -> bf16 hi/lo (tiny)
    dim3 gcw((unsigned)(C_ * C_ / 4 / 256), 7);
    k_cvt_w<<<gcw, 256>>>(w_fq, w_fk, w_fv, w_sq, w_sk, w_sv, w_out);

    // 2. six input projections (tensor cores, activation split fused in loader)
    dim3 gp(C_ / BN, M_ / BM, 6);   // (2, 384, 6)
    k_mma_proj<<<gp, 256>>>(flow_q, flow_k, flow_v, speed_q, speed_k, speed_v);

    // 3. fused attention
    k_attn<<<B_ * N_, 256>>>(kj, vf_fs);

    // 4. four output projections
    dim3 go(C_ / BN, M_ / BM, 4);   // (2, 384, 4)
    k_mma_out<<<go, 256>>>(b_out, (float*)d_out);
}

// round 6
// speedup vs baseline: 1.9520x; 1.3642x over previous
#include <cuda_runtime.h>
#include <cuda_bf16.h>
#include <cstdint>

// ---------------------------------------------------------------------------
// Problem constants
// ---------------------------------------------------------------------------
namespace {
constexpr int B_  = 4;
constexpr int N_  = 1024;
constexpr int T_  = 12;
constexpr int C_  = 256;
constexpr int DK_ = 32;
constexpr int M_  = B_ * N_ * T_;              // 49152 rows
constexpr size_t MC_ = (size_t)M_ * C_;        // 12,582,912 elems per tensor
constexpr float SCALE_ = 0.17677669529663687f; // 1/sqrt(DK)

// GEMM tiling (mma.sync m16n8k16 bf16)
constexpr int BM = 128, BN = 128, BK = 32;
constexpr int NKT = C_ / BK;                   // 8 mainloop iterations
constexpr int LDS = 40;                        // smem row stride in bf16 (80 B)

// Attention smem layout
constexpr int RS = 36;                         // row stride (floats)
constexpr int TS = 444;                        // tile stride (12*36 + 12 pad)
constexpr int PR = 13;                         // P row stride
constexpr int HEAD_SM = 5 * TS + 4 * T_ * PR;  // 2220 + 624 = 2844 floats
constexpr unsigned SMEM_ATTN = 8 * HEAD_SM * 4; // 91,008 bytes
}

// ---------------------------------------------------------------------------
// Device scratch
// ---------------------------------------------------------------------------
__device__ float          g_proj[6 * MC_];      // fp32 projected Q/K/V
__device__ float          g_ctx [4 * MC_];      // fp32 attention contexts
__device__ __nv_bfloat16  g_w_h[7 * C_ * C_];   // bf16 hi of 7 weights
__device__ __nv_bfloat16  g_w_l[7 * C_ * C_];   // bf16 lo of 7 weights

// ---------------------------------------------------------------------------
// PTX helpers (baseline ISA only — no 'a'-suffix features)
// ---------------------------------------------------------------------------
__device__ __forceinline__ uint32_t cvta_s(const void* p) {
    uint32_t a;
    asm("{ .reg .u64 t; cvta.to.shared.u64 t, %1; cvt.u32.u64 %0, t; }"
        : "=r"(a) : "l"(p));
    return a;
}
__device__ __forceinline__ void ldsm4(uint32_t* r, uint32_t addr) {
    asm volatile("ldmatrix.sync.aligned.m8n8.x4.shared.b16 {%0,%1,%2,%3}, [%4];"
                 : "=r"(r[0]), "=r"(r[1]), "=r"(r[2]), "=r"(r[3]) : "r"(addr));
}
__device__ __forceinline__ void mma_bf16(float* d, const uint32_t* a,
                                         const uint32_t* b) {
    asm volatile(
        "mma.sync.aligned.m16n8k16.row.col.f32.bf16.bf16.f32 "
        "{%0,%1,%2,%3}, {%4,%5,%6,%7}, {%8,%9}, {%0,%1,%2,%3};"
        : "+f"(d[0]), "+f"(d[1]), "+f"(d[2]), "+f"(d[3])
        : "r"(a[0]), "r"(a[1]), "r"(a[2]), "r"(a[3]), "r"(b[0]), "r"(b[1]));
}
__device__ __forceinline__ uint32_t pack_bf2(float a, float b) {
    __nv_bfloat162 t = __floats2bfloat162_rn(a, b);
    return *reinterpret_cast<uint32_t*>(&t);
}

// ---------------------------------------------------------------------------
// Weight fp32 -> bf16 hi/lo split (7 weights, 256x256 each; tiny)
// ---------------------------------------------------------------------------
__global__ __launch_bounds__(256) void k_cvt_w(
    const float* __restrict__ w0, const float* __restrict__ w1,
    const float* __restrict__ w2, const float* __restrict__ w3,
    const float* __restrict__ w4, const float* __restrict__ w5,
    const float* __restrict__ w6)
{
    const int z = blockIdx.y;
    const float* s;
    if      (z == 0) s = w0;
    else if (z == 1) s = w1;
    else if (z == 2) s = w2;
    else if (z == 3) s = w3;
    else if (z == 4) s = w4;
    else if (z == 5) s = w5;
    else             s = w6;
    const size_t i = (size_t)blockIdx.x * blockDim.x + threadIdx.x; // float4 idx
    const size_t n4 = (size_t)C_ * C_ / 4;
    if (i >= n4) return;
    float4 v = ((const float4*)s)[i];
    float h0 = __bfloat162float(__float2bfloat16(v.x));
    float h1 = __bfloat162float(__float2bfloat16(v.y));
    float h2 = __bfloat162float(__float2bfloat16(v.z));
    float h3 = __bfloat162float(__float2bfloat16(v.w));
    uint32_t* hp = (uint32_t*)(g_w_h + (size_t)z * C_ * C_) + 2 * i;
    uint32_t* lp = (uint32_t*)(g_w_l + (size_t)z * C_ * C_) + 2 * i;
    hp[0] = pack_bf2(h0, h1);
    hp[1] = pack_bf2(h2, h3);
    lp[0] = pack_bf2(v.x - h0, v.y - h1);
    lp[1] = pack_bf2(v.z - h2, v.w - h3);
}

// ---------------------------------------------------------------------------
// 3-term bf16 mma.sync GEMM:  Y[m,n] = sum_c X[m,c] * W[n,c]  (+ bias)
// (unchanged from the passing R5 kernel)
// ---------------------------------------------------------------------------
template <bool HAS_BIAS>
__device__ __forceinline__ void mma_gemm(
    const float* __restrict__ X,
    const __nv_bfloat16* __restrict__ Wh, const __nv_bfloat16* __restrict__ Wl,
    const float* __restrict__ bias, float* __restrict__ Y)
{
    __shared__ __align__(16) __nv_bfloat16 sAh[BM * LDS];
    __shared__ __align__(16) __nv_bfloat16 sAl[BM * LDS];
    __shared__ __align__(16) __nv_bfloat16 sBh[BN * LDS];
    __shared__ __align__(16) __nv_bfloat16 sBl[BN * LDS];

    const int tid  = threadIdx.x;
    const int lane = tid & 31;
    const int wid  = tid >> 5;
    const int wm   = (wid >> 2) * 64;
    const int wn   = (wid & 3) * 32;
    const int m0 = blockIdx.y * BM;
    const int n0 = blockIdx.x * BN;

    const uint32_t a_ah = cvta_s(sAh), a_al = cvta_s(sAl);
    const uint32_t a_bh = cvta_s(sBh), a_bl = cvta_s(sBl);

    uint32_t aoff[4][2], boff[2][2];
    {
        const int ra = wm + (lane & 7) + ((lane >> 3) & 1) * 8;
        const int ca = (lane >> 4) * 8;
#pragma unroll
        for (int im = 0; im < 4; ++im)
#pragma unroll
            for (int ks = 0; ks < 2; ++ks)
                aoff[im][ks] = (uint32_t)(((ra + im * 16) * LDS + ca + ks * 16) * 2);
        const int rb = wn + (lane & 7) + (lane >> 4) * 8;
        const int cb = ((lane >> 3) & 1) * 8;
#pragma unroll
        for (int ip = 0; ip < 2; ++ip)
#pragma unroll
            for (int ks = 0; ks < 2; ++ks)
                boff[ip][ks] = (uint32_t)(((rb + ip * 16) * LDS + cb + ks * 16) * 2);
    }

    float acc[4][4][4];
#pragma unroll
    for (int im = 0; im < 4; ++im)
#pragma unroll
        for (int in = 0; in < 4; ++in)
#pragma unroll
            for (int q = 0; q < 4; ++q) acc[im][in][q] = 0.f;

    const int lrow = tid >> 1;
    const int lh   = tid & 1;
    const float* xg = X + (size_t)(m0 + lrow) * C_ + lh * 16;
    const __nv_bfloat16* whg = Wh + (size_t)(n0 + lrow) * C_ + lh * 16;
    const __nv_bfloat16* wlg = Wl + (size_t)(n0 + lrow) * C_ + lh * 16;
    uint4* pAh = (uint4*)(sAh + lrow * LDS + lh * 16);
    uint4* pAl = (uint4*)(sAl + lrow * LDS + lh * 16);
    uint4* pBh = (uint4*)(sBh + lrow * LDS + lh * 16);
    uint4* pBl = (uint4*)(sBl + lrow * LDS + lh * 16);

    float4 xv[4];
    uint4  wh2[2], wl2[2];

    {
        const float4* xp = (const float4*)xg;
        xv[0] = xp[0]; xv[1] = xp[1]; xv[2] = xp[2]; xv[3] = xp[3];
        const uint4* whp = (const uint4*)whg;
        const uint4* wlp = (const uint4*)wlg;
        wh2[0] = whp[0]; wh2[1] = whp[1];
        wl2[0] = wlp[0]; wl2[1] = wlp[1];
    }

#pragma unroll 1
    for (int kt = 0; kt < NKT; ++kt) {
        __syncthreads();
        {
            uint32_t hh[8], ll[8];
#pragma unroll
            for (int q = 0; q < 4; ++q) {
                const float4 v = xv[q];
                float h0 = __bfloat162float(__float2bfloat16(v.x));
                float h1 = __bfloat162float(__float2bfloat16(v.y));
                float h2 = __bfloat162float(__float2bfloat16(v.z));
                float h3 = __bfloat162float(__float2bfloat16(v.w));
                hh[q * 2 + 0] = pack_bf2(h0, h1);
                hh[q * 2 + 1] = pack_bf2(h2, h3);
                ll[q * 2 + 0] = pack_bf2(v.x - h0, v.y - h1);
                ll[q * 2 + 1] = pack_bf2(v.z - h2, v.w - h3);
            }
            pAh[0] = make_uint4(hh[0], hh[1], hh[2], hh[3]);
            pAh[1] = make_uint4(hh[4], hh[5], hh[6], hh[7]);
            pAl[0] = make_uint4(ll[0], ll[1], ll[2], ll[3]);
            pAl[1] = make_uint4(ll[4], ll[5], ll[6], ll[7]);
            pBh[0] = wh2[0]; pBh[1] = wh2[1];
            pBl[0] = wl2[0]; pBl[1] = wl2[1];
        }
        __syncthreads();

        if (kt < NKT - 1) {
            const float4* xp = (const float4*)(xg + (kt + 1) * BK);
            xv[0] = xp[0]; xv[1] = xp[1]; xv[2] = xp[2]; xv[3] = xp[3];
            const uint4* whp = (const uint4*)(whg + (kt + 1) * BK);
            const uint4* wlp = (const uint4*)(wlg + (kt + 1) * BK);
            wh2[0] = whp[0]; wh2[1] = whp[1];
            wl2[0] = wlp[0]; wl2[1] = wlp[1];
        }

#pragma unroll
        for (int ks = 0; ks < 2; ++ks) {
            uint32_t ah[4][4], al[4][4], bh[2][4], bl[2][4];
#pragma unroll
            for (int im = 0; im < 4; ++im) {
                ldsm4(ah[im], a_ah + aoff[im][ks]);
                ldsm4(al[im], a_al + aoff[im][ks]);
            }
#pragma unroll
            for (int ip = 0; ip < 2; ++ip) {
                ldsm4(bh[ip], a_bh + boff[ip][ks]);
                ldsm4(bl[ip], a_bl + boff[ip][ks]);
            }
#pragma unroll
            for (int im = 0; im < 4; ++im) {
#pragma unroll
                for (int in = 0; in < 4; ++in) {
                    const uint32_t* bph = &bh[in >> 1][(in & 1) * 2];
                    const uint32_t* bpl = &bl[in >> 1][(in & 1) * 2];
                    mma_bf16(acc[im][in], ah[im], bph);
                    mma_bf16(acc[im][in], ah[im], bpl);
                    mma_bf16(acc[im][in], al[im], bph);
                }
            }
        }
    }

    const int er = lane >> 2;
    const int ec = (lane & 3) * 2;
#pragma unroll
    for (int im = 0; im < 4; ++im) {
#pragma unroll
        for (int in = 0; in < 4; ++in) {
            const int row = m0 + wm + im * 16 + er;
            const int col = n0 + wn + in * 8 + ec;
            float b0 = 0.f, b1 = 0.f;
            if (HAS_BIAS) { b0 = bias[col]; b1 = bias[col + 1]; }
            float2 v0 = make_float2(acc[im][in][0] + b0, acc[im][in][1] + b1);
            float2 v1 = make_float2(acc[im][in][2] + b0, acc[im][in][3] + b1);
            *(float2*)&Y[(size_t)row * C_ + col]       = v0;
            *(float2*)&Y[(size_t)(row + 8) * C_ + col] = v1;
        }
    }
}

__global__ __launch_bounds__(256) void k_mma_proj(
    const float* __restrict__ x0, const float* __restrict__ x1,
    const float* __restrict__ x2, const float* __restrict__ x3,
    const float* __restrict__ x4, const float* __restrict__ x5)
{
    const int z = blockIdx.z;
    const float* X;
    if      (z == 0) X = x0;
    else if (z == 1) X = x1;
    else if (z == 2) X = x2;
    else if (z == 3) X = x3;
    else if (z == 4) X = x4;
    else             X = x5;
    mma_gemm<false>(X, g_w_h + (size_t)z * C_ * C_, g_w_l + (size_t)z * C_ * C_,
                    nullptr, g_proj + (size_t)z * MC_);
}

__global__ __launch_bounds__(256) void k_mma_out(
    const float* __restrict__ bias, float* __restrict__ out)
{
    const int z = blockIdx.z;
    mma_gemm<true>(g_ctx + (size_t)z * MC_,
                   g_w_h + (size_t)6 * C_ * C_, g_w_l + (size_t)6 * C_ * C_,
                   bias, out + (size_t)z * MC_);
}

// ---------------------------------------------------------------------------
// Fused 4-way temporal attention, shuffle-free smem version.
// Grid: B*N CTAs; 8 warps/CTA; warp h owns head h end-to-end (warp-local smem).
//  Phase A: lane=d loads 6 tensors, computes qfs, stages 5 tiles to smem
//           (row stride 36 -> conflict-free), keeps Vf/Vs in registers.
//  Phase B: each lane owns full score rows (attn a, row t): 12 dots of 32 via
//           LDS.128 broadcast, lane-local softmax, normalized P -> smem.
//  Phase C: lane=d computes out[t,d] from P (broadcast) x V (registers).
// ---------------------------------------------------------------------------
__device__ __forceinline__ void attn_row(
    const float* __restrict__ A, const float* __restrict__ Bt,
    float* __restrict__ Prow, int t)
{
    float4 ar[8];
    const float4* ap = (const float4*)(A + t * RS);
#pragma unroll
    for (int q = 0; q < 8; ++q) ar[q] = ap[q];

    float s[T_];
#pragma unroll
    for (int j = 0; j < T_; ++j) {
        const float4* bp = (const float4*)(Bt + j * RS);
        float acc = 0.f;
#pragma unroll
        for (int q = 0; q < 8; ++q) {
            float4 b = bp[q];
            acc += ar[q].x * b.x + ar[q].y * b.y + ar[q].z * b.z + ar[q].w * b.w;
        }
        s[j] = acc;
    }
    float mx = s[0];
#pragma unroll
    for (int j = 1; j < T_; ++j) mx = fmaxf(mx, s[j]);
    float e[T_];
    float sum = 0.f;
#pragma unroll
    for (int j = 0; j < T_; ++j) { e[j] = __expf((s[j] - mx) * SCALE_); sum += e[j]; }
    const float inv = 1.0f / sum;
#pragma unroll
    for (int j = 0; j < T_; ++j) Prow[j] = e[j] * inv;
}

__global__ __launch_bounds__(256) void k_attn(
    const float* __restrict__ kj, const float* __restrict__ vfs)
{
    extern __shared__ float sm[];
    const int bn = blockIdx.x;
    const int h  = threadIdx.x >> 5;
    const int d  = threadIdx.x & 31;

    float* hs   = sm + h * HEAD_SM;
    float* tQf  = hs;
    float* tKf  = hs + 1 * TS;
    float* tQs  = hs + 2 * TS;
    float* tKs  = hs + 3 * TS;
    float* tQfs = hs + 4 * TS;
    float* P    = hs + 5 * TS;      // [4][12][PR]

    const size_t base = (size_t)bn * T_ * C_ + h * DK_ + d;

    const float* Qf = g_proj + 0 * MC_;
    const float* Kf = g_proj + 1 * MC_;
    const float* Vf = g_proj + 2 * MC_;
    const float* Qs = g_proj + 3 * MC_;
    const float* Ks = g_proj + 4 * MC_;
    const float* Vs = g_proj + 5 * MC_;

    float vf[T_], vs[T_];
    // Phase A: load + physics transform + stage tiles
#pragma unroll
    for (int t = 0; t < T_; ++t) {
        const size_t o = base + (size_t)t * C_;
        const float qf = Qf[o];
        const float kf = Kf[o];
        const float qs = Qs[o];
        const float ks = Ks[o];
        vf[t] = Vf[o];
        vs[t] = Vs[o];
        const float den = vfs[t] + 1e-5f;
        const float qfsv = kj[t] * (qs - qs * qs / den);
        tQf [t * RS + d] = qf;
        tKf [t * RS + d] = kf;
        tQs [t * RS + d] = qs;
        tKs [t * RS + d] = ks;
        tQfs[t * RS + d] = qfsv;
    }
    __syncwarp();

    // Phase B: score rows. row r = a*12 + t; lane handles r = lane (and +32).
    {
        const int a0 = d / T_;          // 0..2
        const int t0 = d - a0 * T_;
        const float* Asel[4] = {tQf, tKf, tKs, tQs};
        const float* Bsel[4] = {tKf, tQfs, tQf, tKs};
        attn_row(Asel[a0], Bsel[a0], P + (a0 * T_ + t0) * PR, t0);
        if (d < 16) {
            const int r  = 32 + d;
            const int a1 = r / T_;      // 2..3
            const int t1 = r - a1 * T_;
            attn_row(Asel[a1], Bsel[a1], P + (a1 * T_ + t1) * PR, t1);
        }
    }
    __syncwarp();

    // Phase C: AV. lane=d; V from registers, P broadcast from smem.
#pragma unroll
    for (int a = 0; a < 4; ++a) {
        const float* vv = (a < 2) ? vf : vs;
        float* outp = g_ctx + (size_t)a * MC_ + base;
#pragma unroll
        for (int t = 0; t < T_; ++t) {
            const float* pr = P + (a * T_ + t) * PR;
            float acc = 0.f;
#pragma unroll
            for (int j = 0; j < T_; ++j) acc += pr[j] * vv[j];
            outp[(size_t)t * C_] = acc;
        }
    }
}

// ---------------------------------------------------------------------------
// Entry point
// ---------------------------------------------------------------------------
extern "C" void kernel_launch(void* const* d_in, const int* /*in_sizes*/,
                              int /*n_in*/, void* d_out, int /*out_size*/)
{
    const float* flow_q  = (const float*)d_in[0];
    const float* flow_k  = (const float*)d_in[1];
    const float* flow_v  = (const float*)d_in[2];
    const float* speed_q = (const float*)d_in[3];
    const float* speed_k = (const float*)d_in[4];
    const float* speed_v = (const float*)d_in[5];
    const float* w_fq  = (const float*)d_in[6];
    const float* w_fk  = (const float*)d_in[7];
    const float* w_fv  = (const float*)d_in[8];
    const float* w_sq  = (const float*)d_in[9];
    const float* w_sk  = (const float*)d_in[10];
    const float* w_sv  = (const float*)d_in[11];
    const float* w_out = (const float*)d_in[12];
    const float* b_out = (const float*)d_in[13];
    const float* kj    = (const float*)d_in[14];
    const float* vf_fs = (const float*)d_in[15];

    cudaFuncSetAttribute(k_attn, cudaFuncAttributeMaxDynamicSharedMemorySize,
                         SMEM_ATTN);

    // 1. weight fp32 -> bf16 hi/lo (tiny)
    dim3 gcw((unsigned)(C_ * C_ / 4 / 256), 7);
    k_cvt_w<<<gcw, 256>>>(w_fq, w_fk, w_fv, w_sq, w_sk, w_sv, w_out);

    // 2. six input projections (tensor cores, activation split fused in loader)
    dim3 gp(C_ / BN, M_ / BM, 6);   // (2, 384, 6)
    k_mma_proj<<<gp, 256>>>(flow_q, flow_k, flow_v, speed_q, speed_k, speed_v);

    // 3. fused attention (shuffle-free)
    k_attn<<<B_ * N_, 256, SMEM_ATTN>>>(kj, vf_fs);

    // 4. four output projections
    dim3 go(C_ / BN, M_ / BM, 4);   // (2, 384, 4)
    k_mma_out<<<go, 256>>>(b_out, (float*)d_out);
}